// round 8
// baseline (speedup 1.0000x reference)
#include <cuda_runtime.h>

// SymLoss: B=64, H=3, N=65536, RES=32
// inputs (metadata order):
//   d_in[0] predicted_planes float32 (64,3,4)
//   d_in[1] sample_points    float32 (64,65536,3)
//   d_in[2] voxel_grids      float32 (64,1,32,32,32)   -- UNUSED by reference
//   d_in[3] cp_grids         float32 (64,32,32,32,3)
// output: float32 (1,)

#define BDIM   64
#define HDIM   3
#define NPTS   65536
#define RES    32
#define RES3   (RES * RES * RES)
#define REG_COEF 25.0

#define TPB           256
#define PTS_PER_THD   2
#define PTS_PER_BLK   (TPB * PTS_PER_THD)           // 512
#define CHUNKS_PER_B  (NPTS / PTS_PER_BLK)          // 128
#define MAIN_BLOCKS   (BDIM * CHUNKS_PER_B)         // 8192
#define NG            (PTS_PER_THD * HDIM)          // 6 gathers per thread
#define STAGE_VEC     ((PTS_PER_BLK * 3) / 4)       // 384 float4 loads per block
#define REPACK_BLOCKS ((BDIM * RES3) / TPB)         // 8192 (exact)
#define REPACK_VEC    ((TPB * 3) / 4)               // 192 float4 per repack block

// Scratch: cp_grids repacked to 16B-aligned float4 so each random gather is a
// single LDG.128. 33.5 MB — fits in GB300's ~126 MB L2, so steady-state
// gathers are L2 hits, hidden by batched MLP at full occupancy.
__device__ float4   g_cp[BDIM * RES3];
__device__ double   g_main;      // sum of all distances
__device__ double   g_regsum;    // sum over batches of regularizer
__device__ unsigned g_ticket;    // last-block-finalize ticket

// ---------------------------------------------------------------------------
// 1) fused prep + init:
//    blocks [0, REPACK_BLOCKS): repack cp_grids [B,32,32,32,3] -> float4
//      (coalesced float4 loads -> smem -> stride-3 reads -> STG.128)
//    block  REPACK_BLOCKS:      zero accumulators + compute sum_b reg_b
// ---------------------------------------------------------------------------
__global__ void __launch_bounds__(TPB) prep_init_kernel(
    const float* __restrict__ cp,
    const float* __restrict__ planes)
{
    if (blockIdx.x < REPACK_BLOCKS) {
        // each block repacks TPB=256 records (768 floats = 3072 B, 16B-aligned)
        __shared__ float st[TPB * 3];
        const float4* src = (const float4*)(cp + (size_t)blockIdx.x * TPB * 3);
        float4* st4 = (float4*)st;
        if (threadIdx.x < REPACK_VEC)
            st4[threadIdx.x] = src[threadIdx.x];
        __syncthreads();
        float x = st[3 * threadIdx.x + 0];
        float y = st[3 * threadIdx.x + 1];
        float z = st[3 * threadIdx.x + 2];
        g_cp[blockIdx.x * TPB + threadIdx.x] = make_float4(x, y, z, 0.0f);
        return;
    }

    // ---- init block ----
    int b = threadIdx.x;
    double s = 0.0;
    if (b < BDIM) {
        float nh[HDIM][3];
#pragma unroll
        for (int h = 0; h < HDIM; h++) {
            float nx = planes[(b * HDIM + h) * 4 + 0];
            float ny = planes[(b * HDIM + h) * 4 + 1];
            float nz = planes[(b * HDIM + h) * 4 + 2];
            float inv = rsqrtf(nx * nx + ny * ny + nz * nz);
            nh[h][0] = nx * inv;
            nh[h][1] = ny * inv;
            nh[h][2] = nz * inv;
        }
        double f = 0.0;
#pragma unroll
        for (int h = 0; h < HDIM; h++) {
#pragma unroll
            for (int g = 0; g < HDIM; g++) {
                float a = nh[h][0] * nh[g][0] + nh[h][1] * nh[g][1] +
                          nh[h][2] * nh[g][2] - (h == g ? 1.0f : 0.0f);
                f += (double)a * (double)a;
            }
        }
        s = sqrt(f);
    }

    // reduce s over the block (only threads < 64 carry nonzero values)
    int lane = threadIdx.x & 31;
    int wid  = threadIdx.x >> 5;
#pragma unroll
    for (int o = 16; o > 0; o >>= 1)
        s += __shfl_down_sync(0xffffffffu, s, o);

    __shared__ double ws[TPB / 32];
    if (lane == 0) ws[wid] = s;
    __syncthreads();
    if (threadIdx.x == 0) {
        double tot = 0.0;
#pragma unroll
        for (int w = 0; w < TPB / 32; w++) tot += ws[w];
        g_regsum = tot;
        g_main   = 0.0;
        g_ticket = 0u;
    }
}

// ---------------------------------------------------------------------------
// 2) main: one block per (batch, 512-point chunk).
//    Phase A: stage points through smem (coalesced float4 streaming loads).
//    Phase B: compute all 6 reflected points + indices, issue all 6 float4
//             L2 gathers back-to-back (MLP=6/thread), then consume.
//    Tail:    block-reduce -> double atomic; LAST block writes out[0].
// ---------------------------------------------------------------------------
__global__ void __launch_bounds__(TPB) main_kernel(
    const float* __restrict__ planes,
    const float* __restrict__ sp,
    float* __restrict__ out)
{
    int b     = blockIdx.x / CHUNKS_PER_B;
    int chunk = blockIdx.x % CHUNKS_PER_B;

    // plane params (broadcast loads; identical addresses across the block)
    float nhx[HDIM], nhy[HDIM], nhz[HDIM], dd[HDIM];
#pragma unroll
    for (int h = 0; h < HDIM; h++) {
        float nx = __ldg(&planes[(b * HDIM + h) * 4 + 0]);
        float ny = __ldg(&planes[(b * HDIM + h) * 4 + 1]);
        float nz = __ldg(&planes[(b * HDIM + h) * 4 + 2]);
        float inv = rsqrtf(nx * nx + ny * ny + nz * nz);
        nhx[h] = nx * inv;
        nhy[h] = ny * inv;
        nhz[h] = nz * inv;
        dd[h]  = __ldg(&planes[(b * HDIM + h) * 4 + 3]);
    }

    // Stage this block's 512 points (6 KB) into smem, coalesced float4 loads.
    // Chunk base is 512*3*4 = 6144 B aligned, so float4 loads are aligned.
    __shared__ float spt[PTS_PER_BLK * 3];
    {
        const float4* src =
            (const float4*)(sp + ((size_t)b * NPTS + (size_t)chunk * PTS_PER_BLK) * 3);
        float4* dst = (float4*)spt;
        for (int i = threadIdx.x; i < STAGE_VEC; i += TPB)   // 384: 1.5 iters
            dst[i] = src[i];
    }
    __syncthreads();

    const float4* cpb = g_cp + (size_t)b * RES3;

    // ---- compute all reflected points + indices, issue all 6 gathers ----
    float rx[NG], ry[NG], rz[NG];
    float4 c[NG];
#pragma unroll
    for (int k = 0; k < PTS_PER_THD; k++) {
        int j = k * TPB + threadIdx.x;   // stride-3 smem read: conflict-free
        float px = spt[3 * j + 0];
        float py = spt[3 * j + 1];
        float pz = spt[3 * j + 2];
#pragma unroll
        for (int h = 0; h < HDIM; h++) {
            int q = k * HDIM + h;
            float dist = px * nhx[h] + py * nhy[h] + pz * nhz[h] + dd[h];
            float t  = 2.0f * dist;
            rx[q] = px - t * nhx[h];
            ry[q] = py - t * nhy[h];
            rz[q] = pz - t * nhz[h];
            int ix = min(max((int)floorf(rx[q] * (float)RES), 0), RES - 1);
            int iy = min(max((int)floorf(ry[q] * (float)RES), 0), RES - 1);
            int iz = min(max((int)floorf(rz[q] * (float)RES), 0), RES - 1);
            c[q] = __ldcg(&cpb[(ix * RES + iy) * RES + iz]);
        }
    }

    // ---- consume ----
    float acc = 0.0f;
#pragma unroll
    for (int q = 0; q < NG; q++) {
        float ex = rx[q] - c[q].x;
        float ey = ry[q] - c[q].y;
        float ez = rz[q] - c[q].z;
        acc += sqrtf(ex * ex + ey * ey + ez * ez);
    }

    // block reduction -> one double atomic per block
    int lane = threadIdx.x & 31;
    int wid  = threadIdx.x >> 5;
#pragma unroll
    for (int o = 16; o > 0; o >>= 1)
        acc += __shfl_down_sync(0xffffffffu, acc, o);

    __shared__ float ws[TPB / 32];
    if (lane == 0) ws[wid] = acc;
    __syncthreads();
    if (wid == 0) {
        float v = (lane < TPB / 32) ? ws[lane] : 0.0f;
#pragma unroll
        for (int o = 4; o > 0; o >>= 1)
            v += __shfl_down_sync(0xffffffffu, v, o);
        if (lane == 0) {
            atomicAdd(&g_main, (double)v);
            __threadfence();
            unsigned t = atomicAdd(&g_ticket, 1u);
            if (t == (unsigned)(MAIN_BLOCKS - 1)) {
                // last block: every other block's g_main add is ordered before
                // its ticket increment by the fence above.
                __threadfence();
                double m = *(volatile double*)&g_main;
                double r = *(volatile double*)&g_regsum;
                out[0] = (float)(m / (double)NPTS + REG_COEF * r);
            }
        }
    }
}

// ---------------------------------------------------------------------------
extern "C" void kernel_launch(void* const* d_in, const int* in_sizes, int n_in,
                              void* d_out, int out_size)
{
    const float* planes = (const float*)d_in[0];
    const float* sp     = (const float*)d_in[1];
    // d_in[2] voxel_grids: unused by reference
    const float* cp     = (const float*)d_in[3];
    float* out          = (float*)d_out;

    (void)in_sizes; (void)n_in; (void)out_size;

    prep_init_kernel<<<REPACK_BLOCKS + 1, TPB>>>(cp, planes);
    main_kernel<<<MAIN_BLOCKS, TPB>>>(planes, sp, out);
}

// round 9
// speedup vs baseline: 1.2784x; 1.2784x over previous
#include <cuda_runtime.h>

// SymLoss: B=64, H=3, N=65536, RES=32
// inputs (metadata order):
//   d_in[0] predicted_planes float32 (64,3,4)
//   d_in[1] sample_points    float32 (64,65536,3)
//   d_in[2] voxel_grids      float32 (64,1,32,32,32)   -- UNUSED by reference
//   d_in[3] cp_grids         float32 (64,32,32,32,3)
// output: float32 (1,)

#define BDIM   64
#define HDIM   3
#define NPTS   65536
#define RES    32
#define RES3   (RES * RES * RES)
#define REG_COEF 25.0

#define TPB           256
#define PTS_PER_THD   8                              // 4 groups of 2 points
#define GROUPS        4
#define PTS_PER_GRP   2
#define NGG           (PTS_PER_GRP * HDIM)           // 6 gathers per group
#define PTS_PER_BLK   (TPB * PTS_PER_THD)            // 2048
#define CHUNKS_PER_B  (NPTS / PTS_PER_BLK)           // 32
#define MAIN_BLOCKS   (BDIM * CHUNKS_PER_B)          // 2048
#define STAGE_VEC     ((PTS_PER_BLK * 3) / 4)        // 1536 float4 per block
#define REPACK_BLOCKS ((BDIM * RES3) / TPB)          // 8192 (exact)
#define REPACK_VEC    ((TPB * 3) / 4)                // 192 float4 per repack block

// Scratch: cp_grids repacked to 16B-aligned float4 so each random gather is a
// single LDG.128. 33.5 MB — fits in GB300's ~126 MB L2, so steady-state
// gathers are L2 hits, hidden by batched MLP.
__device__ float4   g_cp[BDIM * RES3];
__device__ double   g_main;      // sum of all distances
__device__ double   g_regsum;    // sum over batches of regularizer
__device__ unsigned g_ticket;    // last-block-finalize ticket

// ---------------------------------------------------------------------------
// 1) fused prep + init:
//    blocks [0, REPACK_BLOCKS): repack cp_grids [B,32,32,32,3] -> float4
//    block  REPACK_BLOCKS:      zero accumulators + compute sum_b reg_b
// ---------------------------------------------------------------------------
__global__ void __launch_bounds__(TPB) prep_init_kernel(
    const float* __restrict__ cp,
    const float* __restrict__ planes)
{
    if (blockIdx.x < REPACK_BLOCKS) {
        // each block repacks TPB=256 records (768 floats = 3072 B, 16B-aligned)
        __shared__ float st[TPB * 3];
        const float4* src = (const float4*)(cp + (size_t)blockIdx.x * TPB * 3);
        float4* st4 = (float4*)st;
        if (threadIdx.x < REPACK_VEC)
            st4[threadIdx.x] = src[threadIdx.x];
        __syncthreads();
        float x = st[3 * threadIdx.x + 0];
        float y = st[3 * threadIdx.x + 1];
        float z = st[3 * threadIdx.x + 2];
        g_cp[blockIdx.x * TPB + threadIdx.x] = make_float4(x, y, z, 0.0f);
        return;
    }

    // ---- init block ----
    int b = threadIdx.x;
    double s = 0.0;
    if (b < BDIM) {
        float nh[HDIM][3];
#pragma unroll
        for (int h = 0; h < HDIM; h++) {
            float nx = planes[(b * HDIM + h) * 4 + 0];
            float ny = planes[(b * HDIM + h) * 4 + 1];
            float nz = planes[(b * HDIM + h) * 4 + 2];
            float inv = rsqrtf(nx * nx + ny * ny + nz * nz);
            nh[h][0] = nx * inv;
            nh[h][1] = ny * inv;
            nh[h][2] = nz * inv;
        }
        double f = 0.0;
#pragma unroll
        for (int h = 0; h < HDIM; h++) {
#pragma unroll
            for (int g = 0; g < HDIM; g++) {
                float a = nh[h][0] * nh[g][0] + nh[h][1] * nh[g][1] +
                          nh[h][2] * nh[g][2] - (h == g ? 1.0f : 0.0f);
                f += (double)a * (double)a;
            }
        }
        s = sqrt(f);
    }

    int lane = threadIdx.x & 31;
    int wid  = threadIdx.x >> 5;
#pragma unroll
    for (int o = 16; o > 0; o >>= 1)
        s += __shfl_down_sync(0xffffffffu, s, o);

    __shared__ double ws[TPB / 32];
    if (lane == 0) ws[wid] = s;
    __syncthreads();
    if (threadIdx.x == 0) {
        double tot = 0.0;
#pragma unroll
        for (int w = 0; w < TPB / 32; w++) tot += ws[w];
        g_regsum = tot;
        g_main   = 0.0;
        g_ticket = 0u;
    }
}

// ---------------------------------------------------------------------------
// 2) main: one block per (batch, 2048-point chunk).  2048 blocks total
//    (~2.3 waves at 6 blocks/SM -> wave-transition loss minimized, per-block
//    reduction overhead amortized 4x vs the 8192-block version).
//    Per group of 2 points: compute 6 indices, issue 6 float4 L2 gathers
//    back-to-back, consume. Groups are independent -> scheduler overlaps
//    group g+1 issue with group g scoreboard wait.
// ---------------------------------------------------------------------------
__global__ void __launch_bounds__(TPB) main_kernel(
    const float* __restrict__ planes,
    const float* __restrict__ sp,
    float* __restrict__ out)
{
    int b     = blockIdx.x / CHUNKS_PER_B;
    int chunk = blockIdx.x % CHUNKS_PER_B;

    // plane params (broadcast loads; identical addresses across the block)
    float nhx[HDIM], nhy[HDIM], nhz[HDIM], dd[HDIM];
#pragma unroll
    for (int h = 0; h < HDIM; h++) {
        float nx = __ldg(&planes[(b * HDIM + h) * 4 + 0]);
        float ny = __ldg(&planes[(b * HDIM + h) * 4 + 1]);
        float nz = __ldg(&planes[(b * HDIM + h) * 4 + 2]);
        float inv = rsqrtf(nx * nx + ny * ny + nz * nz);
        nhx[h] = nx * inv;
        nhy[h] = ny * inv;
        nhz[h] = nz * inv;
        dd[h]  = __ldg(&planes[(b * HDIM + h) * 4 + 3]);
    }

    // Stage this block's 2048 points (24 KB) into smem, coalesced float4.
    // Chunk base is 2048*3*4 = 24576 B aligned, so float4 loads are aligned.
    __shared__ float spt[PTS_PER_BLK * 3];
    {
        const float4* src =
            (const float4*)(sp + ((size_t)b * NPTS + (size_t)chunk * PTS_PER_BLK) * 3);
        float4* dst = (float4*)spt;
#pragma unroll
        for (int k = 0; k < STAGE_VEC / TPB; k++)   // 6 iters, exact
            dst[k * TPB + threadIdx.x] = src[k * TPB + threadIdx.x];
    }
    __syncthreads();

    const float4* cpb = g_cp + (size_t)b * RES3;

    float acc = 0.0f;
#pragma unroll
    for (int g = 0; g < GROUPS; g++) {
        // ---- compute 2 points x 3 heads: indices + issue 6 gathers ----
        float rx[NGG], ry[NGG], rz[NGG];
        float4 c[NGG];
#pragma unroll
        for (int k = 0; k < PTS_PER_GRP; k++) {
            int j = (g * PTS_PER_GRP + k) * TPB + threadIdx.x;  // stride-3: conflict-free
            float px = spt[3 * j + 0];
            float py = spt[3 * j + 1];
            float pz = spt[3 * j + 2];
#pragma unroll
            for (int h = 0; h < HDIM; h++) {
                int q = k * HDIM + h;
                float dist = px * nhx[h] + py * nhy[h] + pz * nhz[h] + dd[h];
                float t  = 2.0f * dist;
                rx[q] = px - t * nhx[h];
                ry[q] = py - t * nhy[h];
                rz[q] = pz - t * nhz[h];
                int ix = min(max((int)floorf(rx[q] * (float)RES), 0), RES - 1);
                int iy = min(max((int)floorf(ry[q] * (float)RES), 0), RES - 1);
                int iz = min(max((int)floorf(rz[q] * (float)RES), 0), RES - 1);
                c[q] = __ldcg(&cpb[(ix * RES + iy) * RES + iz]);
            }
        }
        // ---- consume ----
#pragma unroll
        for (int q = 0; q < NGG; q++) {
            float ex = rx[q] - c[q].x;
            float ey = ry[q] - c[q].y;
            float ez = rz[q] - c[q].z;
            acc += sqrtf(ex * ex + ey * ey + ez * ez);
        }
    }

    // block reduction -> one double atomic per block
    int lane = threadIdx.x & 31;
    int wid  = threadIdx.x >> 5;
#pragma unroll
    for (int o = 16; o > 0; o >>= 1)
        acc += __shfl_down_sync(0xffffffffu, acc, o);

    __shared__ float ws[TPB / 32];
    if (lane == 0) ws[wid] = acc;
    __syncthreads();
    if (wid == 0) {
        float v = (lane < TPB / 32) ? ws[lane] : 0.0f;
#pragma unroll
        for (int o = 4; o > 0; o >>= 1)
            v += __shfl_down_sync(0xffffffffu, v, o);
        if (lane == 0) {
            atomicAdd(&g_main, (double)v);
            __threadfence();
            unsigned t = atomicAdd(&g_ticket, 1u);
            if (t == (unsigned)(MAIN_BLOCKS - 1)) {
                // last block: every other block's g_main add is ordered before
                // its ticket increment by the fence above.
                __threadfence();
                double m = *(volatile double*)&g_main;
                double r = *(volatile double*)&g_regsum;
                out[0] = (float)(m / (double)NPTS + REG_COEF * r);
            }
        }
    }
}

// ---------------------------------------------------------------------------
extern "C" void kernel_launch(void* const* d_in, const int* in_sizes, int n_in,
                              void* d_out, int out_size)
{
    const float* planes = (const float*)d_in[0];
    const float* sp     = (const float*)d_in[1];
    // d_in[2] voxel_grids: unused by reference
    const float* cp     = (const float*)d_in[3];
    float* out          = (float*)d_out;

    (void)in_sizes; (void)n_in; (void)out_size;

    prep_init_kernel<<<REPACK_BLOCKS + 1, TPB>>>(cp, planes);
    main_kernel<<<MAIN_BLOCKS, TPB>>>(planes, sp, out);
}